// round 4
// baseline (speedup 1.0000x reference)
#include <cuda_runtime.h>
#include <cstdint>

#define NN 100000
#define NE 1600000
#define DD 128
#define SCAN_B 512
#define NSCAN ((NN + SCAN_B - 1) / SCAN_B)

// ---------------- scratch (static device globals) ----------------
__device__ float g_hn[NN * DD];     // (h @ W) * src_norm  (messages)
__device__ float g_h[NN * DD];      // aggregated + transformed activations
__device__ int   g_cin[NN];
__device__ int   g_cout[NN];
__device__ int   g_fill[NN];
__device__ int   g_off[NN + 1];     // CSR row offsets (by dst)
__device__ int   g_csr[NE];         // src ids sorted by dst
__device__ float g_srcnorm[NN];
__device__ float g_dstnorm[NN];
__device__ int   g_bsum[NSCAN];
__device__ int   g_bpre[NSCAN];

// ---------------- CSR build ----------------
__global__ void k_zero(int n) {
    int i = blockIdx.x * blockDim.x + threadIdx.x;
    if (i < n) { g_cin[i] = 0; g_cout[i] = 0; g_fill[i] = 0; }
}

__global__ void k_count(const int* __restrict__ src,
                        const int* __restrict__ dst, int E) {
    int i = blockIdx.x * blockDim.x + threadIdx.x;
    if (i < E) {
        atomicAdd(&g_cout[src[i]], 1);
        atomicAdd(&g_cin[dst[i]], 1);
    }
}

__global__ void k_norm(int n) {
    int i = blockIdx.x * blockDim.x + threadIdx.x;
    if (i < n) {
        g_srcnorm[i] = rsqrtf((float)max(g_cout[i], 1));
        g_dstnorm[i] = rsqrtf((float)max(g_cin[i], 1));
    }
}

__global__ void k_scan1(int n) {
    __shared__ int s[SCAN_B];
    int t = threadIdx.x;
    int g = blockIdx.x * SCAN_B + t;
    int v = (g < n) ? g_cin[g] : 0;
    s[t] = v;
    __syncthreads();
    for (int o = 1; o < SCAN_B; o <<= 1) {
        int x = (t >= o) ? s[t - o] : 0;
        __syncthreads();
        s[t] += x;
        __syncthreads();
    }
    if (g < n) g_off[g] = s[t] - v;
    if (t == SCAN_B - 1) g_bsum[blockIdx.x] = s[t];
}

__global__ void k_scan2(int nb, int n) {
    if (threadIdx.x == 0 && blockIdx.x == 0) {
        int run = 0;
        for (int b = 0; b < nb; b++) { g_bpre[b] = run; run += g_bsum[b]; }
        g_off[n] = run;
    }
}

__global__ void k_scan3(int n) {
    int g = blockIdx.x * blockDim.x + threadIdx.x;
    if (g < n) g_off[g] += g_bpre[g / SCAN_B];
}

__global__ void k_fill(const int* __restrict__ src,
                       const int* __restrict__ dst, int E) {
    int e = blockIdx.x * blockDim.x + threadIdx.x;
    if (e < E) {
        int d = dst[e];
        int p = g_off[d] + atomicAdd(&g_fill[d], 1);
        g_csr[p] = src[e];
    }
}

// ---------------- GEMM: g_hn = A @ W, rows scaled by src_norm ----------------
// 128x128 tile, 256 threads, 8x8 per thread, BK=16.
// Inner product uses packed fma.rn.f32x2 (FFMA2): B pairs come straight from
// 64-bit smem loads (adjacent columns), A is broadcast-packed via mov.b64.
__global__ void __launch_bounds__(256)
gemm_kernel(const float* __restrict__ A, const float* __restrict__ W, int M) {
    __shared__ float As[16][132];
    __shared__ float Bs[16 * 128];

    const int t  = threadIdx.x;
    const int tx = t & 15;
    const int ty = t >> 4;
    const int row0 = blockIdx.x * 128;

    unsigned long long acc2[8][4];   // [row][colpair]: (2*j, 2*j+1) packed fp32x2
#pragma unroll
    for (int i = 0; i < 8; i++)
#pragma unroll
        for (int j = 0; j < 4; j++) acc2[i][j] = 0ull;

    for (int kk = 0; kk < 128; kk += 16) {
#pragma unroll
        for (int i = 0; i < 8; i++) {
            int idx = t + i * 256;
            int m = idx >> 4, k = idx & 15;
            int gr = row0 + m;
            As[k][m] = (gr < M) ? A[gr * 128 + kk + k] : 0.f;
        }
#pragma unroll
        for (int i = 0; i < 8; i++) {
            int idx = t + i * 256;
            int k = idx >> 7, n = idx & 127;
            Bs[k * 128 + n] = W[(kk + k) * 128 + n];
        }
        __syncthreads();

#pragma unroll
        for (int k = 0; k < 16; k++) {
            float4 a0 = *(const float4*)&As[k][ty * 8];
            float4 a1 = *(const float4*)&As[k][ty * 8 + 4];
            // B pairs: 64-bit loads of adjacent columns (little-endian: low = first col)
            ulonglong2 bq0 = *(const ulonglong2*)&Bs[k * 128 + tx * 4];
            ulonglong2 bq1 = *(const ulonglong2*)&Bs[k * 128 + 64 + tx * 4];
            unsigned long long bp[4] = {bq0.x, bq0.y, bq1.x, bq1.y};

            float av[8] = {a0.x, a0.y, a0.z, a0.w, a1.x, a1.y, a1.z, a1.w};
            unsigned long long ap[8];
#pragma unroll
            for (int i = 0; i < 8; i++)
                asm("mov.b64 %0, {%1, %1};" : "=l"(ap[i]) : "f"(av[i]));

#pragma unroll
            for (int i = 0; i < 8; i++)
#pragma unroll
                for (int j = 0; j < 4; j++)
                    asm("fma.rn.f32x2 %0, %1, %2, %3;"
                        : "=l"(acc2[i][j])
                        : "l"(ap[i]), "l"(bp[j]), "l"(acc2[i][j]));
        }
        __syncthreads();
    }

    // epilogue: unpack, scale rows by src_norm, write messages
#pragma unroll
    for (int i = 0; i < 8; i++) {
        int gr = row0 + ty * 8 + i;
        if (gr < M) {
            float s = g_srcnorm[gr];
            float c[8];
#pragma unroll
            for (int j = 0; j < 4; j++)
                asm("mov.b64 {%0, %1}, %2;"
                    : "=f"(c[2 * j]), "=f"(c[2 * j + 1]) : "l"(acc2[i][j]));
            float4 o0 = make_float4(c[0] * s, c[1] * s, c[2] * s, c[3] * s);
            float4 o1 = make_float4(c[4] * s, c[5] * s, c[6] * s, c[7] * s);
            *(float4*)&g_hn[gr * 128 + tx * 4] = o0;
            *(float4*)&g_hn[gr * 128 + 64 + tx * 4] = o1;
        }
    }
}

// ---------------- CSR aggregation: one warp per dst node --------------------
template <int RELU>
__global__ void __launch_bounds__(256)
agg_kernel(const float* __restrict__ bias, float* __restrict__ out, int n) {
    int w = blockIdx.x * 8 + (threadIdx.x >> 5);
    if (w >= n) return;
    int lane = threadIdx.x & 31;

    int start = g_off[w];
    int end   = g_off[w + 1];

    float4 acc = make_float4(0.f, 0.f, 0.f, 0.f);

    for (int i = start; i < end; i += 32) {
        int myid = (i + lane < end) ? g_csr[i + lane] : 0;
        int cnt = min(32, end - i);
#pragma unroll 4
        for (int j = 0; j < cnt; j++) {
            int s = __shfl_sync(0xffffffffu, myid, j);
            const float4 v = *(const float4*)&g_hn[(size_t)s * 128 + lane * 4];
            acc.x += v.x; acc.y += v.y; acc.z += v.z; acc.w += v.w;
        }
    }

    float dn = g_dstnorm[w];
    float4 b = *(const float4*)&bias[lane * 4];
    float4 o = make_float4(fmaf(acc.x, dn, b.x), fmaf(acc.y, dn, b.y),
                           fmaf(acc.z, dn, b.z), fmaf(acc.w, dn, b.w));
    if (RELU) {
        o.x = fmaxf(o.x, 0.f); o.y = fmaxf(o.y, 0.f);
        o.z = fmaxf(o.z, 0.f); o.w = fmaxf(o.w, 0.f);
    }
    *(float4*)&out[(size_t)w * 128 + lane * 4] = o;
}

// ---------------- launch ----------------
extern "C" void kernel_launch(void* const* d_in, const int* in_sizes, int n_in,
                              void* d_out, int out_size) {
    const float* feats = (const float*)d_in[0];
    const float* W1 = (const float*)d_in[1];
    const float* b1 = (const float*)d_in[2];
    const float* W2 = (const float*)d_in[3];
    const float* b2 = (const float*)d_in[4];
    const float* W3 = (const float*)d_in[5];
    const float* b3 = (const float*)d_in[6];
    const int* src = (const int*)d_in[7];
    const int* dst = (const int*)d_in[8];
    float* out = (float*)d_out;

    const int M = in_sizes[0] / DD;   // 100000
    const int E = in_sizes[7];        // 1600000

    float* hp = nullptr;
    cudaGetSymbolAddress((void**)&hp, g_h);

    const int nb_node = (M + 255) / 256;
    const int nb_edge = (E + 255) / 256;
    const int nb_gemm = (M + 127) / 128;
    const int nb_agg  = (M + 7) / 8;
    const int nscan   = (M + SCAN_B - 1) / SCAN_B;

    // ---- build norms + CSR (by dst) ----
    k_zero<<<nb_node, 256>>>(M);
    k_count<<<nb_edge, 256>>>(src, dst, E);
    k_norm<<<nb_node, 256>>>(M);
    k_scan1<<<nscan, SCAN_B>>>(M);
    k_scan2<<<1, 32>>>(nscan, M);
    k_scan3<<<nb_node, 256>>>(M);
    k_fill<<<nb_edge, 256>>>(src, dst, E);

    // ---- layer 1 ----
    gemm_kernel<<<nb_gemm, 256>>>(feats, W1, M);
    agg_kernel<1><<<nb_agg, 256>>>(b1, hp, M);
    // ---- layer 2 ----
    gemm_kernel<<<nb_gemm, 256>>>(hp, W2, M);
    agg_kernel<1><<<nb_agg, 256>>>(b2, hp, M);
    // ---- layer 3 ----
    gemm_kernel<<<nb_gemm, 256>>>(hp, W3, M);
    agg_kernel<0><<<nb_agg, 256>>>(b3, out, M);
}